// round 16
// baseline (speedup 1.0000x reference)
#include <cuda_runtime.h>
#include <math.h>
#include <stdint.h>

#define Bsz 2
#define Sl  2048
#define Dm  1024
#define Hn  16
#define HKn 4
#define HDn 64
#define DKn 64
#define DVn 64
#define NCH 32
#define MS  (Bsz*Sl)

__device__ float    g_q[Bsz*Sl*Hn*HDn];
__device__ float    g_k[Bsz*Sl*HKn*HDn];
__device__ float    g_z[Bsz*Sl*DKn];
__device__ uint32_t g_attn2[Bsz*Sl*Hn*HDn];
__device__ uint32_t g_mem2[Bsz*Sl*DVn];
__device__ uint32_t g_q2[Bsz*Sl*Hn*HDn];
__device__ uint32_t g_k2[Bsz*Sl*HKn*HDn];
__device__ uint32_t g_v2[Bsz*HKn*(Sl/2)*128];
__device__ uint32_t g_x2[Bsz*Sl*Dm];
__device__ uint32_t g_wq2[Dm*Hn*HDn];
__device__ uint32_t g_wk2[Dm*HKn*HDn];
__device__ uint32_t g_wv2[Dm*HKn*HDn];
__device__ uint32_t g_wz2[Dm*DKn];
__device__ uint32_t g_wo2[Hn*HDn*Dm];
__device__ uint32_t g_wmo2[DVn*Dm];

__device__ __forceinline__ uint32_t f2tf(float x) {
    uint32_t u; asm("cvt.rna.tf32.f32 %0, %1;" : "=r"(u) : "f"(x)); return u;
}
__device__ __forceinline__ float ex2(float x) {
    float y; asm("ex2.approx.f32 %0, %1;" : "=f"(y) : "f"(x)); return y;
}
__device__ __forceinline__ int colperm(int d) {
    return (d & ~7) | ((d & 3) << 1) | ((d >> 2) & 1);
}
__device__ __forceinline__ unsigned su32(const void* p) {
    unsigned a;
    asm("{.reg .u64 t; cvta.to.shared.u64 t, %1; cvt.u32.u64 %0, t;}" : "=r"(a) : "l"(p));
    return a;
}
#define CP16(dst, src) asm volatile("cp.async.ca.shared.global [%0], [%1], 16;" :: "r"(dst), "l"(src))
#define CPCOMMIT()     asm volatile("cp.async.commit_group;")
#define CPWAITALL()    asm volatile("cp.async.wait_group 0;")

__device__ __forceinline__ void mma8(float d[4], const uint32_t a[4], const uint32_t b[2]) {
    asm volatile(
        "mma.sync.aligned.m16n8k8.row.col.f32.tf32.tf32.f32 "
        "{%0,%1,%2,%3}, {%4,%5,%6,%7}, {%8,%9}, {%0,%1,%2,%3};"
        : "+f"(d[0]), "+f"(d[1]), "+f"(d[2]), "+f"(d[3])
        : "r"(a[0]), "r"(a[1]), "r"(a[2]), "r"(a[3]), "r"(b[0]), "r"(b[1]));
}

// ---------------------------------------------------------------------------
// tf32 conversion kernels: A = critical path (x + proj weights), B = side.
// ---------------------------------------------------------------------------
__global__ void cvtA_kernel(const float* __restrict__ x,  const float* __restrict__ wq,
                            const float* __restrict__ wk, const float* __restrict__ wv,
                            const float* __restrict__ wz,
                            uint32_t* __restrict__ x2,  uint32_t* __restrict__ wq2,
                            uint32_t* __restrict__ wk2, uint32_t* __restrict__ wv2,
                            uint32_t* __restrict__ wz2) {
    const int S0 = Bsz*Sl*Dm/4;
    const int S1 = S0 + Dm*Hn*HDn/4;
    const int S2 = S1 + Dm*HKn*HDn/4;
    const int S3 = S2 + Dm*HKn*HDn/4;
    const int S4 = S3 + Dm*DKn/4;
    int idx = blockIdx.x * blockDim.x + threadIdx.x;
    if (idx >= S4) return;
    const float* src; uint32_t* dst; int off;
    if (idx < S0)      { src = x;  dst = x2;  off = idx; }
    else if (idx < S1) { src = wq; dst = wq2; off = idx - S0; }
    else if (idx < S2) { src = wk; dst = wk2; off = idx - S1; }
    else if (idx < S3) { src = wv; dst = wv2; off = idx - S2; }
    else               { src = wz; dst = wz2; off = idx - S3; }
    float4 t = *(const float4*)&src[off * 4];
    uint4 u;
    u.x = f2tf(t.x); u.y = f2tf(t.y); u.z = f2tf(t.z); u.w = f2tf(t.w);
    *(uint4*)&dst[off * 4] = u;
}

__global__ void cvtB_kernel(const float* __restrict__ wo, const float* __restrict__ wmo,
                            uint32_t* __restrict__ wo2, uint32_t* __restrict__ wmo2) {
    const int S0 = Hn*HDn*Dm/4;
    const int S1 = S0 + DVn*Dm/4;
    int idx = blockIdx.x * blockDim.x + threadIdx.x;
    if (idx >= S1) return;
    const float* src; uint32_t* dst; int off;
    if (idx < S0) { src = wo;  dst = wo2;  off = idx; }
    else          { src = wmo; dst = wmo2; off = idx - S0; }
    float4 t = *(const float4*)&src[off * 4];
    uint4 u;
    u.x = f2tf(t.x); u.y = f2tf(t.y); u.z = f2tf(t.z); u.w = f2tf(t.w);
    *(uint4*)&dst[off * 4] = u;
}

// ===========================================================================
// TF32 GEMM core v3: BM=128, BN=128, BK=16, 256 thr (8 warps, 4x2).
// ===========================================================================
#define AXS 36
#define BXS 136
#define GEMM_SM_WORDS (2*128*AXS + 2*16*BXS)
#define GEMM_SM_BYTES (GEMM_SM_WORDS * 4)

__device__ __forceinline__ void g_issue(const uint32_t* __restrict__ A,
                                        const uint32_t* __restrict__ B,
                                        int K, int N, int row0, int col0, int k0,
                                        int tid, unsigned Asd, unsigned Bsd) {
    #pragma unroll
    for (int i = 0; i < 2; i++) {
        int vec = tid + i * 256;
        int m = vec >> 2, kq = vec & 3;
        CP16(Asd + (unsigned)((m * AXS + kq * 4) * 4),
             &A[(size_t)(row0 + m) * K + k0 + kq * 4]);
        int kk = vec >> 5, nq = vec & 31;
        int col = col0 + nq * 4;
        if (col < N)
            CP16(Bsd + (unsigned)((kk * BXS + nq * 4) * 4),
                 &B[(size_t)(k0 + kk) * N + col]);
    }
}

__device__ __forceinline__ void g_mma(const uint32_t* As, const uint32_t* Bs,
                                      int lane, int wm, int wn, float d[2][8][4]) {
    #pragma unroll
    for (int ks = 0; ks < 16; ks += 8) {
        int kc = ks + (lane & 3);
        uint32_t a[2][4], b[8][2];
        #pragma unroll
        for (int mt = 0; mt < 2; mt++) {
            int r = wm * 32 + mt * 16 + (lane >> 2);
            a[mt][0] = As[r * AXS + kc];
            a[mt][1] = As[(r + 8) * AXS + kc];
            a[mt][2] = As[r * AXS + kc + 4];
            a[mt][3] = As[(r + 8) * AXS + kc + 4];
        }
        #pragma unroll
        for (int nt = 0; nt < 8; nt++) {
            int n = wn * 64 + nt * 8 + (lane >> 2);
            b[nt][0] = Bs[kc * BXS + n];
            b[nt][1] = Bs[(kc + 4) * BXS + n];
        }
        #pragma unroll
        for (int mt = 0; mt < 2; mt++)
            #pragma unroll
            for (int nt = 0; nt < 8; nt++)
                mma8(d[mt][nt], a[mt], b[nt]);
    }
}

__device__ __forceinline__ void g_epilogue(float d[2][8][4], float* __restrict__ C,
                                           int N, int row0, int col0,
                                           int lane, int wm, int wn) {
    #pragma unroll
    for (int mt = 0; mt < 2; mt++) {
        #pragma unroll
        for (int nt = 0; nt < 8; nt++) {
            int r = row0 + wm * 32 + mt * 16 + (lane >> 2);
            int cc = col0 + wn * 64 + nt * 8 + 2 * (lane & 3);
            if (cc < N) {
                *(float2*)&C[(size_t)r * N + cc]       = make_float2(d[mt][nt][0], d[mt][nt][1]);
                *(float2*)&C[(size_t)(r + 8) * N + cc] = make_float2(d[mt][nt][2], d[mt][nt][3]);
            }
        }
    }
}

__device__ __forceinline__ void v2store(uint32_t* __restrict__ v2, int r, int cc, float val) {
    int s = r & (Sl - 1), b = r >> 11;
    int kh = cc >> 6, d = cc & 63;
    size_t idx = ((size_t)(b * HKn + kh) * (Sl / 2) + (s >> 3) * 4 + ((s >> 1) & 3)) * 128
               + 2 * d + (s & 1);
    v2[idx] = f2tf(val);
}

// ---------------------------------------------------------------------------
// Fused projection GEMM with ct offset: ct0=12/grid=(1,32) computes z only;
// ct0=0/grid=(12,32) computes q,k,v.
// ---------------------------------------------------------------------------
__global__ __launch_bounds__(256, 2)
void proj_kernel(const uint32_t* __restrict__ x,
                 const uint32_t* __restrict__ Wq, const uint32_t* __restrict__ Wk,
                 const uint32_t* __restrict__ Wv, const uint32_t* __restrict__ Wz,
                 float* __restrict__ q, float* __restrict__ kout,
                 uint32_t* __restrict__ v2, float* __restrict__ z, int ct0) {
    extern __shared__ uint32_t gsm[];
    uint32_t* As = gsm;
    uint32_t* Bs = gsm + 2 * 128 * AXS;
    int tid = threadIdx.x;
    int lane = tid & 31, warp = tid >> 5;
    int wm = warp >> 1, wn = warp & 1;
    int ct = blockIdx.x + ct0;
    int row0 = blockIdx.y * 128;
    const uint32_t* B; float* C; int N, col0; bool isV = false;
    if (ct < 8)       { B = Wq; C = q;    N = 1024; col0 = ct * 128; }
    else if (ct < 10) { B = Wk; C = kout; N = 256;  col0 = (ct - 8) * 128; }
    else if (ct < 12) { B = Wv; C = nullptr; N = 256; col0 = (ct - 10) * 128; isV = true; }
    else              { B = Wz; C = z;    N = 64;   col0 = 0; }

    float d[2][8][4] = {};
    unsigned Asd = su32(As), Bsd = su32(Bs);
    g_issue(x, B, 1024, N, row0, col0, 0, tid, Asd, Bsd);
    CPCOMMIT(); CPWAITALL();
    __syncthreads();
    for (int k0 = 0; k0 < 1024; k0 += 16) {
        int cur = (k0 >> 4) & 1;
        if (k0 + 16 < 1024) {
            g_issue(x, B, 1024, N, row0, col0, k0 + 16, tid,
                    Asd + (unsigned)((cur ^ 1) * 128 * AXS * 4),
                    Bsd + (unsigned)((cur ^ 1) * 16 * BXS * 4));
            CPCOMMIT();
        }
        g_mma(As + cur * 128 * AXS, Bs + cur * 16 * BXS, lane, wm, wn, d);
        if (k0 + 16 < 1024) CPWAITALL();
        __syncthreads();
    }
    if (!isV) {
        g_epilogue(d, C, N, row0, col0, lane, wm, wn);
    } else {
        #pragma unroll
        for (int mt = 0; mt < 2; mt++) {
            #pragma unroll
            for (int nt = 0; nt < 8; nt++) {
                int r = row0 + wm * 32 + mt * 16 + (lane >> 2);
                int cc = col0 + wn * 64 + nt * 8 + 2 * (lane & 3);
                v2store(v2, r,     cc,     d[mt][nt][0]);
                v2store(v2, r,     cc + 1, d[mt][nt][1]);
                v2store(v2, r + 8, cc,     d[mt][nt][2]);
                v2store(v2, r + 8, cc + 1, d[mt][nt][3]);
            }
        }
    }
}

// ---------------------------------------------------------------------------
// Dual GEMM (tf32 inputs): grid=(8,32), block=256.
// ---------------------------------------------------------------------------
__global__ __launch_bounds__(256, 2)
void dual_gemm_kernel(const uint32_t* __restrict__ A1, const uint32_t* __restrict__ B1, int K1,
                      const uint32_t* __restrict__ A2, const uint32_t* __restrict__ B2, int K2,
                      float* __restrict__ C, int N) {
    extern __shared__ uint32_t gsm[];
    uint32_t* As = gsm;
    uint32_t* Bs = gsm + 2 * 128 * AXS;
    int tid = threadIdx.x;
    int lane = tid & 31, warp = tid >> 5;
    int wm = warp >> 1, wn = warp & 1;
    int row0 = blockIdx.y * 128, col0 = blockIdx.x * 128;
    float d[2][8][4] = {};
    unsigned Asd = su32(As), Bsd = su32(Bs);
    #pragma unroll
    for (int ph = 0; ph < 2; ph++) {
        const uint32_t* A = ph ? A2 : A1;
        const uint32_t* B = ph ? B2 : B1;
        int K = ph ? K2 : K1;
        g_issue(A, B, K, N, row0, col0, 0, tid, Asd, Bsd);
        CPCOMMIT(); CPWAITALL();
        __syncthreads();
        for (int k0 = 0; k0 < K; k0 += 16) {
            int cur = (k0 >> 4) & 1;
            if (k0 + 16 < K) {
                g_issue(A, B, K, N, row0, col0, k0 + 16, tid,
                        Asd + (unsigned)((cur ^ 1) * 128 * AXS * 4),
                        Bsd + (unsigned)((cur ^ 1) * 16 * BXS * 4));
                CPCOMMIT();
            }
            g_mma(As + cur * 128 * AXS, Bs + cur * 16 * BXS, lane, wm, wn, d);
            if (k0 + 16 < K) CPWAITALL();
            __syncthreads();
        }
    }
    g_epilogue(d, C, N, row0, col0, lane, wm, wn);
}

// ---------------------------------------------------------------------------
// RoPE (smem inv-freq table).
// ---------------------------------------------------------------------------
#define QSCALE 0.18033688f   // 0.125 * log2(e)

__global__ void rope_kernel(const float* __restrict__ qp, const float* __restrict__ kp,
                            uint32_t* __restrict__ q2, uint32_t* __restrict__ k2) {
    __shared__ float sinv[32];
    if (threadIdx.x < 32)
        sinv[threadIdx.x] = powf(500000.0f, -(float)(2 * threadIdx.x) / 64.0f);
    __syncthreads();
    int idx = blockIdx.x * blockDim.x + threadIdx.x;
    const int qtot = Bsz * Sl * Hn * 32;
    const int ktot = Bsz * Sl * HKn * 32;
    const float* src; uint32_t* dst; int nheads; bool isq;
    if (idx < qtot) { src = qp; dst = q2; nheads = Hn; isq = true; }
    else { idx -= qtot; if (idx >= ktot) return; src = kp; dst = k2; nheads = HKn; isq = false; }
    int j = idx & 31;
    int h = (idx >> 5) % nheads;
    int s = ((idx >> 5) / nheads) % Sl;
    int b = idx / (32 * nheads * Sl);
    float ang = (float)s * sinv[j];
    float c, sn;
    __sincosf(ang, &sn, &c);
    size_t base = ((size_t)(b * Sl + s) * nheads + h) * 64;
    float u1 = src[base + j], u2 = src[base + j + 32];
    float r1 = u1 * c - u2 * sn;
    float r2 = u2 * c + u1 * sn;
    if (isq) { r1 *= QSCALE; r2 *= QSCALE; }
    dst[base + colperm(j)]      = f2tf(r1);
    dst[base + colperm(j + 32)] = f2tf(r2);
}

// ---------------------------------------------------------------------------
// TF32 flash attention v6 (R15 best): no-max softmax, raw-bit P, l via
// ones-column mma, sigma-permuted V. 128 threads, 2 CTAs/SM.
// ---------------------------------------------------------------------------
#define QST 72
#define KST 72
#define VST 144
#define ATTN_WORDS (128*QST + 2*64*KST + 2*32*VST)
#define ATTN_BYTES (ATTN_WORDS * 4)
#define TF_ONE 0x3F800000u

__global__ __launch_bounds__(128, 2)
void attn_kernel(const uint32_t* __restrict__ q2, const uint32_t* __restrict__ k2,
                 const uint32_t* __restrict__ v2, uint32_t* __restrict__ o2) {
    extern __shared__ uint32_t smu[];
    uint32_t* qs = smu;
    uint32_t* ks = qs + 128 * QST;
    uint32_t* vs = ks + 2 * 64 * KST;

    int qt = (int)gridDim.x - 1 - (int)blockIdx.x;
    int bh = blockIdx.y;
    int b = bh >> 4, h = bh & 15, kh = h >> 2;
    int tid = threadIdx.x;
    int lane = tid & 31, w = tid >> 5;
    int g = lane >> 2, c4 = lane & 3;
    int row_base = w * 32 + g;

    size_t qbase = ((size_t)(b * Sl + qt * 128) * Hn + h) * 64;
    size_t kvbase = ((size_t)(b * Sl) * HKn + kh) * 64;
    size_t v2base0 = (size_t)(b * HKn + kh) * (Sl / 2) * 128;
    int ktmax = 2 * qt + 1;

    {
        unsigned qd = su32(qs);
        #pragma unroll
        for (int i = 0; i < 16; i++) {
            int vec = tid + i * 128;
            int r = vec >> 4, ch = vec & 15;
            CP16(qd + (unsigned)((r * QST + ch * 4) * 4),
                 &q2[qbase + (size_t)r * Hn * 64 + ch * 4]);
        }
        unsigned kd = su32(ks), vd = su32(vs);
        #pragma unroll
        for (int i = 0; i < 8; i++) {
            int vec = tid + i * 128;
            int c = vec >> 4, dq = vec & 15;
            CP16(kd + (unsigned)((c * KST + dq * 4) * 4),
                 &k2[kvbase + (size_t)c * HKn * 64 + dq * 4]);
            int row = vec >> 5, ch = vec & 31;
            CP16(vd + (unsigned)((row * VST + ch * 4) * 4),
                 &v2[v2base0 + (size_t)row * 128 + ch * 4]);
        }
        CPCOMMIT();
    }

    float accL[2][4] = {};
    float accO[2][8][4] = {};
    const uint32_t bones[2] = { TF_ONE, TF_ONE };
    CPWAITALL();
    __syncthreads();

    for (int kt = 0; kt <= ktmax; kt++) {
        const uint32_t* kb = ks + (kt & 1) * 64 * KST;
        const uint32_t* vb = vs + (kt & 1) * 32 * VST;

        if (kt < ktmax) {
            unsigned kd = su32(ks + ((kt + 1) & 1) * 64 * KST);
            unsigned vd = su32(vs + ((kt + 1) & 1) * 32 * VST);
            size_t kbase = kvbase + (size_t)(kt + 1) * 64 * HKn * 64;
            size_t vbase = v2base0 + (size_t)(kt + 1) * 32 * 128;
            #pragma unroll
            for (int i = 0; i < 8; i++) {
                int vec = tid + i * 128;
                int c = vec >> 4, dq = vec & 15;
                CP16(kd + (unsigned)((c * KST + dq * 4) * 4),
                     &k2[kbase + (size_t)c * HKn * 64 + dq * 4]);
                int row = vec >> 5, ch = vec & 31;
                CP16(vd + (unsigned)((row * VST + ch * 4) * 4),
                     &v2[vbase + (size_t)row * 128 + ch * 4]);
            }
            CPCOMMIT();
        }

        // ---- QK^T ----
        float sc[2][8][4] = {};
        #pragma unroll
        for (int t8 = 0; t8 < 8; t8++) {
            int pc = t8 * 8 + 2 * c4;
            uint32_t a[2][4];
            #pragma unroll
            for (int mt = 0; mt < 2; mt++) {
                uint2 ua0 = *(const uint2*)&qs[(row_base + mt * 16) * QST + pc];
                uint2 ua1 = *(const uint2*)&qs[(row_base + mt * 16 + 8) * QST + pc];
                a[mt][0] = ua0.x; a[mt][1] = ua1.x; a[mt][2] = ua0.y; a[mt][3] = ua1.y;
            }
            #pragma unroll
            for (int nt = 0; nt < 8; nt++) {
                int n = nt * 8 + g;
                uint2 ub = *(const uint2*)&kb[n * KST + pc];
                uint32_t bb[2] = { ub.x, ub.y };
                mma8(sc[0][nt], a[0], bb);
                mma8(sc[1][nt], a[1], bb);
            }
        }

        // ---- causal mask ----
        if (kt >= 2 * qt) {
            #pragma unroll
            for (int mt = 0; mt < 2; mt++) {
                int rg0 = qt * 128 + row_base + mt * 16, rg1 = rg0 + 8;
                #pragma unroll
                for (int nt = 0; nt < 8; nt++) {
                    int cg = kt * 64 + nt * 8 + 2 * c4;
                    if (cg > rg0)     sc[mt][nt][0] = -1e30f;
                    if (cg + 1 > rg0) sc[mt][nt][1] = -1e30f;
                    if (cg > rg1)     sc[mt][nt][2] = -1e30f;
                    if (cg + 1 > rg1) sc[mt][nt][3] = -1e30f;
                }
            }
        }

        // ---- softmax numerator ----
        #pragma unroll
        for (int mt = 0; mt < 2; mt++)
            #pragma unroll
            for (int nt = 0; nt < 8; nt++) {
                sc[mt][nt][0] = ex2(sc[mt][nt][0]);
                sc[mt][nt][1] = ex2(sc[mt][nt][1]);
                sc[mt][nt][2] = ex2(sc[mt][nt][2]);
                sc[mt][nt][3] = ex2(sc[mt][nt][3]);
            }

        // ---- P @ V + l via ones-mma ----
        #pragma unroll
        for (int t = 0; t < 8; t++) {
            uint32_t a[2][4];
            #pragma unroll
            for (int mt = 0; mt < 2; mt++) {
                a[mt][0] = __float_as_uint(sc[mt][t][0]);
                a[mt][1] = __float_as_uint(sc[mt][t][2]);
                a[mt][2] = __float_as_uint(sc[mt][t][1]);
                a[mt][3] = __float_as_uint(sc[mt][t][3]);
            }
            int vrow = t * 4 + c4;
            #pragma unroll
            for (int nt = 0; nt < 8; nt++) {
                int dcol = nt * 8 + g;
                uint2 ub = *(const uint2*)&vb[vrow * VST + 2 * dcol];
                uint32_t bb[2] = { ub.x, ub.y };
                mma8(accO[0][nt], a[0], bb);
                mma8(accO[1][nt], a[1], bb);
            }
            mma8(accL[0], a[0], bones);
            mma8(accL[1], a[1], bones);
        }

        if (kt < ktmax) CPWAITALL();
        __syncthreads();
    }

    // ---- epilogue ----
    #pragma unroll
    for (int mt = 0; mt < 2; mt++) {
        float il0 = 1.f / accL[mt][0];
        float il1 = 1.f / accL[mt][2];
        size_t ob0 = ((size_t)(b * Sl + qt * 128 + row_base + mt * 16) * Hn + h) * 64;
        size_t ob1 = ((size_t)(b * Sl + qt * 128 + row_base + mt * 16 + 8) * Hn + h) * 64;
        #pragma unroll
        for (int nt = 0; nt < 8; nt++) {
            int dcol = nt * 8 + 2 * c4;
            uint2 u0, u1;
            u0.x = f2tf(accO[mt][nt][0] * il0); u0.y = f2tf(accO[mt][nt][1] * il0);
            u1.x = f2tf(accO[mt][nt][2] * il1); u1.y = f2tf(accO[mt][nt][3] * il1);
            *(uint2*)&o2[ob0 + dcol] = u0;
            *(uint2*)&o2[ob1 + dcol] = u1;
        }
    }
}

// ---------------------------------------------------------------------------
// Chunked delta-rule memory scan (side stream, forked right after z).
// ---------------------------------------------------------------------------
__global__ __launch_bounds__(256)
void memscan_kernel(const float* __restrict__ z,
                    const float* __restrict__ M_init,
                    const float* __restrict__ w_eta, const float* __restrict__ b_eta,
                    const float* __restrict__ w_alpha, const float* __restrict__ b_alpha,
                    const float* __restrict__ w_gate, const float* __restrict__ b_gate,
                    uint32_t* __restrict__ mem_out) {
    __shared__ float Ms[64][65];
    __shared__ float chs[64][65];
    __shared__ float red2[16][64];
    __shared__ float se[64], sa[64], sg[64], rnrm[64];
    __shared__ float kmean[64], vt[64], diffv[64];
    __shared__ float swe[64], swa[64], swg[64];
    __shared__ float redw[8];
    __shared__ float sc_eta, sc_alpha, sc_gate, sc_scale;

    int b = blockIdx.x;
    int tid = threadIdx.x;
    int tx = tid & 15, ty = tid >> 4;
    int lane = tid & 31, warp = tid >> 5;
    int tok = tid >> 2, part = tid & 3;
    float be = b_eta[0], ba = b_alpha[0], bg = b_gate[0];

    if (tid < 64) { swe[tid] = w_eta[tid]; swa[tid] = w_alpha[tid]; swg[tid] = w_gate[tid]; }
    #pragma unroll
    for (int i = 0; i < 16; i++) {
        int idx = tid + i * 256;
        Ms[idx >> 6][idx & 63] = M_init[idx];
    }
    __syncthreads();

    for (int c = 0; c < NCH; c++) {
        #pragma unroll
        for (int i = 0; i < 16; i++) {
            int idx = tid + i * 256;
            chs[idx >> 6][idx & 63] = z[((size_t)b * Sl + c * 64 + (idx >> 6)) * 64 + (idx & 63)];
        }
        __syncthreads();

        float o4[4][4] = {};
        #pragma unroll
        for (int d = 0; d < 64; d++) {
            float a0 = chs[ty*4+0][d], a1 = chs[ty*4+1][d];
            float a2 = chs[ty*4+2][d], a3 = chs[ty*4+3][d];
            float m0 = Ms[tx*4+0][d], m1 = Ms[tx*4+1][d];
            float m2 = Ms[tx*4+2][d], m3 = Ms[tx*4+3][d];
            o4[0][0] += a0*m0; o4[0][1] += a0*m1; o4[0][2] += a0*m2; o4[0][3] += a0*m3;
            o4[1][0] += a1*m0; o4[1][1] += a1*m1; o4[1][2] += a1*m2; o4[1][3] += a1*m3;
            o4[2][0] += a2*m0; o4[2][1] += a2*m1; o4[2][2] += a2*m2; o4[2][3] += a2*m3;
            o4[3][0] += a3*m0; o4[3][1] += a3*m1; o4[3][2] += a3*m2; o4[3][3] += a3*m3;
        }
        #pragma unroll
        for (int i = 0; i < 4; i++)
            #pragma unroll
            for (int j = 0; j < 4; j++)
                mem_out[((size_t)b * Sl + c * 64 + ty * 4 + i) * 64 + tx * 4 + j] = f2tf(o4[i][j]);
        #pragma unroll
        for (int j = 0; j < 4; j++)
            red2[ty][tx * 4 + j] = o4[0][j] + o4[1][j] + o4[2][j] + o4[3][j];
        __syncthreads();

        {
            float de = 0.f, da = 0.f, dg = 0.f, nn = 0.f;
            int d0 = part * 16;
            #pragma unroll
            for (int dd = 0; dd < 16; dd++) {
                float xv = chs[tok][d0 + dd];
                de = fmaf(xv, swe[d0 + dd], de);
                da = fmaf(xv, swa[d0 + dd], da);
                dg = fmaf(xv, swg[d0 + dd], dg);
                nn = fmaf(xv, xv, nn);
            }
            de += __shfl_xor_sync(0xffffffffu, de, 1); de += __shfl_xor_sync(0xffffffffu, de, 2);
            da += __shfl_xor_sync(0xffffffffu, da, 1); da += __shfl_xor_sync(0xffffffffu, da, 2);
            dg += __shfl_xor_sync(0xffffffffu, dg, 1); dg += __shfl_xor_sync(0xffffffffu, dg, 2);
            nn += __shfl_xor_sync(0xffffffffu, nn, 1); nn += __shfl_xor_sync(0xffffffffu, nn, 2);
            if (part == 0) {
                se[tok] = 0.2f / (1.f + __expf(-(de + be)));
                sa[tok] = 0.5f + 0.5f / (1.f + __expf(-(da + ba)));
                sg[tok] = 1.f / (1.f + __expf(-(dg + bg)));
                rnrm[tok] = 1.f / fmaxf(sqrtf(nn), 1e-6f);
            }
        }
        __syncthreads();

        {
            float s = 0.f, s2 = 0.f;
            #pragma unroll
            for (int t = 0; t < 16; t++)
                s = fmaf(chs[part * 16 + t][tok], rnrm[part * 16 + t], s);
            #pragma unroll
            for (int yy = 0; yy < 4; yy++) s2 += red2[part * 4 + yy][tok];
            s  += __shfl_xor_sync(0xffffffffu, s, 1);  s  += __shfl_xor_sync(0xffffffffu, s, 2);
            s2 += __shfl_xor_sync(0xffffffffu, s2, 1); s2 += __shfl_xor_sync(0xffffffffu, s2, 2);
            if (part == 0) { kmean[tok] = s * (1.f / 64.f); vt[tok] = s2 * (1.f / 64.f); }
        }
        __syncthreads();

        if (tid < 32) {
            float e = se[tid] + se[tid + 32];
            float a = sa[tid] + sa[tid + 32];
            float gg = sg[tid] + sg[tid + 32];
            #pragma unroll
            for (int st = 16; st; st >>= 1) {
                e  += __shfl_xor_sync(0xffffffffu, e, st);
                a  += __shfl_xor_sync(0xffffffffu, a, st);
                gg += __shfl_xor_sync(0xffffffffu, gg, st);
            }
            if (tid == 0) {
                sc_eta = e * (1.f / 64.f);
                sc_alpha = a * (1.f / 64.f);
                sc_gate = gg * (1.f / 64.f);
            }
        }
        {
            float s = 0.f;
            int d0 = part * 16;
            #pragma unroll
            for (int dd = 0; dd < 16; dd++)
                s = fmaf(Ms[tok][d0 + dd], kmean[d0 + dd], s);
            s += __shfl_xor_sync(0xffffffffu, s, 1);
            s += __shfl_xor_sync(0xffffffffu, s, 2);
            if (part == 0) diffv[tok] = vt[tok] - s;
        }
        __syncthreads();

        float eg = sc_eta * sc_gate, al = sc_alpha;
        float ss2 = 0.f;
        #pragma unroll
        for (int i = 0; i < 16; i++) {
            int idx = tid + i * 256;
            int vv = idx >> 6, d = idx & 63;
            float mn = al * Ms[vv][d] + eg * diffv[vv] * kmean[d];
            Ms[vv][d] = mn;
            ss2 = fmaf(mn, mn, ss2);
        }
        #pragma unroll
        for (int st = 16; st; st >>= 1) ss2 += __shfl_xor_sync(0xffffffffu, ss2, st);
        if (lane == 0) redw[warp] = ss2;
        __syncthreads();
        if (tid == 0) {
            float fro = sqrtf(redw[0] + redw[1] + redw[2] + redw[3] +
                              redw[4] + redw[5] + redw[6] + redw[7]);
            sc_scale = fminf(1.f, 30.f / fmaxf(fro, 1e-6f));
        }
        __syncthreads();
        #pragma unroll
        for (int i = 0; i < 16; i++) {
            int idx = tid + i * 256;
            Ms[idx >> 6][idx & 63] *= sc_scale;
        }
        __syncthreads();
    }
}

// ---------------------------------------------------------------------------
extern "C" void kernel_launch(void* const* d_in, const int* in_sizes, int n_in,
                              void* d_out, int out_size) {
    const float* x       = (const float*)d_in[0];
    const float* Wq      = (const float*)d_in[1];
    const float* Wk      = (const float*)d_in[2];
    const float* Wv      = (const float*)d_in[3];
    const float* Wo      = (const float*)d_in[4];
    const float* Wmemin  = (const float*)d_in[5];
    const float* Wmemout = (const float*)d_in[6];
    const float* M_init  = (const float*)d_in[7];
    const float* w_eta   = (const float*)d_in[8];
    const float* b_eta   = (const float*)d_in[9];
    const float* w_alpha = (const float*)d_in[10];
    const float* b_alpha = (const float*)d_in[11];
    const float* w_gate  = (const float*)d_in[12];
    const float* b_gate  = (const float*)d_in[13];
    float* out = (float*)d_out;

    float *q, *k, *z;
    uint32_t *attn2, *mem2, *q2, *k2, *v2;
    uint32_t *x2, *wq2, *wk2, *wv2, *wz2, *wo2, *wmo2;
    cudaGetSymbolAddress((void**)&q, g_q);
    cudaGetSymbolAddress((void**)&k, g_k);
    cudaGetSymbolAddress((void**)&z, g_z);
    cudaGetSymbolAddress((void**)&attn2, g_attn2);
    cudaGetSymbolAddress((void**)&mem2, g_mem2);
    cudaGetSymbolAddress((void**)&q2, g_q2);
    cudaGetSymbolAddress((void**)&k2, g_k2);
    cudaGetSymbolAddress((void**)&v2, g_v2);
    cudaGetSymbolAddress((void**)&x2, g_x2);
    cudaGetSymbolAddress((void**)&wq2, g_wq2);
    cudaGetSymbolAddress((void**)&wk2, g_wk2);
    cudaGetSymbolAddress((void**)&wv2, g_wv2);
    cudaGetSymbolAddress((void**)&wz2, g_wz2);
    cudaGetSymbolAddress((void**)&wo2, g_wo2);
    cudaGetSymbolAddress((void**)&wmo2, g_wmo2);

    static cudaStream_t s2 = nullptr;
    static cudaEvent_t evZ = nullptr, evM = nullptr;
    static int inited = 0;
    if (!inited) {
        cudaStreamCreateWithFlags(&s2, cudaStreamNonBlocking);
        cudaEventCreateWithFlags(&evZ, cudaEventDisableTiming);
        cudaEventCreateWithFlags(&evM, cudaEventDisableTiming);
        cudaFuncSetAttribute(attn_kernel,
                             cudaFuncAttributeMaxDynamicSharedMemorySize, ATTN_BYTES);
        cudaFuncSetAttribute(proj_kernel,
                             cudaFuncAttributeMaxDynamicSharedMemorySize, GEMM_SM_BYTES);
        cudaFuncSetAttribute(dual_gemm_kernel,
                             cudaFuncAttributeMaxDynamicSharedMemorySize, GEMM_SM_BYTES);
        inited = 1;
    }

    // Side stream: convert output-GEMM weights (off critical path).
    {
        int total4 = (Hn*HDn*Dm + DVn*Dm) / 4;
        cvtB_kernel<<<(total4 + 255) / 256, 256, 0, s2>>>(Wo, Wmemout, wo2, wmo2);
    }
    // Critical path: convert x + projection weights.
    {
        int total4 = (Bsz*Sl*Dm + Dm*Hn*HDn + 2*Dm*HKn*HDn + Dm*DKn) / 4;
        cvtA_kernel<<<(total4 + 255) / 256, 256>>>(x, Wq, Wk, Wv, Wmemin,
                                                   x2, wq2, wk2, wv2, wz2);
    }

    // z FIRST (tiny GEMM), then fork memscan so it hides under proj+attention.
    proj_kernel<<<dim3(1, 32), 256, GEMM_SM_BYTES>>>(x2, wq2, wk2, wv2, wz2,
                                                     q, k, v2, z, 12);
    cudaEventRecord(evZ, 0);
    cudaStreamWaitEvent(s2, evZ, 0);
    memscan_kernel<<<Bsz, 256, 0, s2>>>(z, M_init, w_eta, b_eta, w_alpha, b_alpha,
                                        w_gate, b_gate, mem2);
    cudaEventRecord(evM, s2);

    // Remaining projections (q, k, v)
    proj_kernel<<<dim3(12, 32), 256, GEMM_SM_BYTES>>>(x2, wq2, wk2, wv2, wz2,
                                                      q, k, v2, z, 0);

    // RoPE + tf32 convert + permute
    {
        int total = Bsz * Sl * (Hn + HKn) * 32;
        rope_kernel<<<(total + 255) / 256, 256>>>(q, k, q2, k2);
    }

    // Attention
    attn_kernel<<<dim3(Sl/128, Bsz*Hn), 128, ATTN_BYTES>>>(q2, k2, v2, attn2);

    // Join memscan (and cvtB), then fused output GEMM
    cudaStreamWaitEvent((cudaStream_t)0, evM, 0);
    dual_gemm_kernel<<<dim3(8, 32), 256, GEMM_SM_BYTES>>>(attn2, wo2, Hn*HDn,
                                                          mem2, wmo2, DVn, out, Dm);
}

// round 17
// speedup vs baseline: 1.1173x; 1.1173x over previous
#include <cuda_runtime.h>
#include <math.h>
#include <stdint.h>

#define Bsz 2
#define Sl  2048
#define Dm  1024
#define Hn  16
#define HKn 4
#define HDn 64
#define DKn 64
#define DVn 64
#define NCH 32
#define MS  (Bsz*Sl)

__device__ float    g_q[Bsz*Sl*Hn*HDn];
__device__ float    g_k[Bsz*Sl*HKn*HDn];
__device__ float    g_z[Bsz*Sl*DKn];
__device__ uint32_t g_attn2[Bsz*Sl*Hn*HDn];
__device__ uint32_t g_mem2[Bsz*Sl*DVn];
__device__ uint32_t g_q2[Bsz*Sl*Hn*HDn];
__device__ uint32_t g_k2[Bsz*Sl*HKn*HDn];
__device__ uint32_t g_v2[Bsz*HKn*(Sl/2)*128];
__device__ uint32_t g_x2[Bsz*Sl*Dm];
__device__ uint32_t g_wq2[Dm*Hn*HDn];
__device__ uint32_t g_wk2[Dm*HKn*HDn];
__device__ uint32_t g_wv2[Dm*HKn*HDn];
__device__ uint32_t g_wz2[Dm*DKn];
__device__ uint32_t g_wo2[Hn*HDn*Dm];
__device__ uint32_t g_wmo2[DVn*Dm];

__device__ __forceinline__ uint32_t f2tf(float x) {
    uint32_t u; asm("cvt.rna.tf32.f32 %0, %1;" : "=r"(u) : "f"(x)); return u;
}
__device__ __forceinline__ float ex2(float x) {
    float y; asm("ex2.approx.f32 %0, %1;" : "=f"(y) : "f"(x)); return y;
}
__device__ __forceinline__ int colperm(int d) {
    return (d & ~7) | ((d & 3) << 1) | ((d >> 2) & 1);
}
__device__ __forceinline__ unsigned su32(const void* p) {
    unsigned a;
    asm("{.reg .u64 t; cvta.to.shared.u64 t, %1; cvt.u32.u64 %0, t;}" : "=r"(a) : "l"(p));
    return a;
}
#define CP16(dst, src) asm volatile("cp.async.ca.shared.global [%0], [%1], 16;" :: "r"(dst), "l"(src))
#define CPCOMMIT()     asm volatile("cp.async.commit_group;")
#define CPWAITALL()    asm volatile("cp.async.wait_group 0;")

__device__ __forceinline__ void mma8(float d[4], const uint32_t a[4], const uint32_t b[2]) {
    asm volatile(
        "mma.sync.aligned.m16n8k8.row.col.f32.tf32.tf32.f32 "
        "{%0,%1,%2,%3}, {%4,%5,%6,%7}, {%8,%9}, {%0,%1,%2,%3};"
        : "+f"(d[0]), "+f"(d[1]), "+f"(d[2]), "+f"(d[3])
        : "r"(a[0]), "r"(a[1]), "r"(a[2]), "r"(a[3]), "r"(b[0]), "r"(b[1]));
}

// ---------------------------------------------------------------------------
// tf32 conversion kernels: A = critical path (x + proj weights), B = side.
// ---------------------------------------------------------------------------
__global__ void cvtA_kernel(const float* __restrict__ x,  const float* __restrict__ wq,
                            const float* __restrict__ wk, const float* __restrict__ wv,
                            const float* __restrict__ wz,
                            uint32_t* __restrict__ x2,  uint32_t* __restrict__ wq2,
                            uint32_t* __restrict__ wk2, uint32_t* __restrict__ wv2,
                            uint32_t* __restrict__ wz2) {
    const int S0 = Bsz*Sl*Dm/4;
    const int S1 = S0 + Dm*Hn*HDn/4;
    const int S2 = S1 + Dm*HKn*HDn/4;
    const int S3 = S2 + Dm*HKn*HDn/4;
    const int S4 = S3 + Dm*DKn/4;
    int idx = blockIdx.x * blockDim.x + threadIdx.x;
    if (idx >= S4) return;
    const float* src; uint32_t* dst; int off;
    if (idx < S0)      { src = x;  dst = x2;  off = idx; }
    else if (idx < S1) { src = wq; dst = wq2; off = idx - S0; }
    else if (idx < S2) { src = wk; dst = wk2; off = idx - S1; }
    else if (idx < S3) { src = wv; dst = wv2; off = idx - S2; }
    else               { src = wz; dst = wz2; off = idx - S3; }
    float4 t = *(const float4*)&src[off * 4];
    uint4 u;
    u.x = f2tf(t.x); u.y = f2tf(t.y); u.z = f2tf(t.z); u.w = f2tf(t.w);
    *(uint4*)&dst[off * 4] = u;
}

__global__ void cvtB_kernel(const float* __restrict__ wo, const float* __restrict__ wmo,
                            uint32_t* __restrict__ wo2, uint32_t* __restrict__ wmo2) {
    const int S0 = Hn*HDn*Dm/4;
    const int S1 = S0 + DVn*Dm/4;
    int idx = blockIdx.x * blockDim.x + threadIdx.x;
    if (idx >= S1) return;
    const float* src; uint32_t* dst; int off;
    if (idx < S0) { src = wo;  dst = wo2;  off = idx; }
    else          { src = wmo; dst = wmo2; off = idx - S0; }
    float4 t = *(const float4*)&src[off * 4];
    uint4 u;
    u.x = f2tf(t.x); u.y = f2tf(t.y); u.z = f2tf(t.z); u.w = f2tf(t.w);
    *(uint4*)&dst[off * 4] = u;
}

// ===========================================================================
// TF32 GEMM core v3: BM=128, BN=128, BK=16, 256 thr (8 warps, 4x2).
// ===========================================================================
#define AXS 36
#define BXS 136
#define GEMM_SM_WORDS (2*128*AXS + 2*16*BXS)
#define GEMM_SM_BYTES (GEMM_SM_WORDS * 4)

__device__ __forceinline__ void g_issue(const uint32_t* __restrict__ A,
                                        const uint32_t* __restrict__ B,
                                        int K, int N, int row0, int col0, int k0,
                                        int tid, unsigned Asd, unsigned Bsd) {
    #pragma unroll
    for (int i = 0; i < 2; i++) {
        int vec = tid + i * 256;
        int m = vec >> 2, kq = vec & 3;
        CP16(Asd + (unsigned)((m * AXS + kq * 4) * 4),
             &A[(size_t)(row0 + m) * K + k0 + kq * 4]);
        int kk = vec >> 5, nq = vec & 31;
        int col = col0 + nq * 4;
        if (col < N)
            CP16(Bsd + (unsigned)((kk * BXS + nq * 4) * 4),
                 &B[(size_t)(k0 + kk) * N + col]);
    }
}

__device__ __forceinline__ void g_mma(const uint32_t* As, const uint32_t* Bs,
                                      int lane, int wm, int wn, float d[2][8][4]) {
    #pragma unroll
    for (int ks = 0; ks < 16; ks += 8) {
        int kc = ks + (lane & 3);
        uint32_t a[2][4], b[8][2];
        #pragma unroll
        for (int mt = 0; mt < 2; mt++) {
            int r = wm * 32 + mt * 16 + (lane >> 2);
            a[mt][0] = As[r * AXS + kc];
            a[mt][1] = As[(r + 8) * AXS + kc];
            a[mt][2] = As[r * AXS + kc + 4];
            a[mt][3] = As[(r + 8) * AXS + kc + 4];
        }
        #pragma unroll
        for (int nt = 0; nt < 8; nt++) {
            int n = wn * 64 + nt * 8 + (lane >> 2);
            b[nt][0] = Bs[kc * BXS + n];
            b[nt][1] = Bs[(kc + 4) * BXS + n];
        }
        #pragma unroll
        for (int mt = 0; mt < 2; mt++)
            #pragma unroll
            for (int nt = 0; nt < 8; nt++)
                mma8(d[mt][nt], a[mt], b[nt]);
    }
}

__device__ __forceinline__ void g_epilogue(float d[2][8][4], float* __restrict__ C,
                                           int N, int row0, int col0,
                                           int lane, int wm, int wn) {
    #pragma unroll
    for (int mt = 0; mt < 2; mt++) {
        #pragma unroll
        for (int nt = 0; nt < 8; nt++) {
            int r = row0 + wm * 32 + mt * 16 + (lane >> 2);
            int cc = col0 + wn * 64 + nt * 8 + 2 * (lane & 3);
            if (cc < N) {
                *(float2*)&C[(size_t)r * N + cc]       = make_float2(d[mt][nt][0], d[mt][nt][1]);
                *(float2*)&C[(size_t)(r + 8) * N + cc] = make_float2(d[mt][nt][2], d[mt][nt][3]);
            }
        }
    }
}

__device__ __forceinline__ void v2store(uint32_t* __restrict__ v2, int r, int cc, float val) {
    int s = r & (Sl - 1), b = r >> 11;
    int kh = cc >> 6, d = cc & 63;
    size_t idx = ((size_t)(b * HKn + kh) * (Sl / 2) + (s >> 3) * 4 + ((s >> 1) & 3)) * 128
               + 2 * d + (s & 1);
    v2[idx] = f2tf(val);
}

// ---------------------------------------------------------------------------
// Fused projection GEMM with ct offset: ct0=12/grid=(1,32) computes z only
// (launched on the side stream, concurrent with the main 12-tile launch).
// ---------------------------------------------------------------------------
__global__ __launch_bounds__(256, 2)
void proj_kernel(const uint32_t* __restrict__ x,
                 const uint32_t* __restrict__ Wq, const uint32_t* __restrict__ Wk,
                 const uint32_t* __restrict__ Wv, const uint32_t* __restrict__ Wz,
                 float* __restrict__ q, float* __restrict__ kout,
                 uint32_t* __restrict__ v2, float* __restrict__ z, int ct0) {
    extern __shared__ uint32_t gsm[];
    uint32_t* As = gsm;
    uint32_t* Bs = gsm + 2 * 128 * AXS;
    int tid = threadIdx.x;
    int lane = tid & 31, warp = tid >> 5;
    int wm = warp >> 1, wn = warp & 1;
    int ct = blockIdx.x + ct0;
    int row0 = blockIdx.y * 128;
    const uint32_t* B; float* C; int N, col0; bool isV = false;
    if (ct < 8)       { B = Wq; C = q;    N = 1024; col0 = ct * 128; }
    else if (ct < 10) { B = Wk; C = kout; N = 256;  col0 = (ct - 8) * 128; }
    else if (ct < 12) { B = Wv; C = nullptr; N = 256; col0 = (ct - 10) * 128; isV = true; }
    else              { B = Wz; C = z;    N = 64;   col0 = 0; }

    float d[2][8][4] = {};
    unsigned Asd = su32(As), Bsd = su32(Bs);
    g_issue(x, B, 1024, N, row0, col0, 0, tid, Asd, Bsd);
    CPCOMMIT(); CPWAITALL();
    __syncthreads();
    for (int k0 = 0; k0 < 1024; k0 += 16) {
        int cur = (k0 >> 4) & 1;
        if (k0 + 16 < 1024) {
            g_issue(x, B, 1024, N, row0, col0, k0 + 16, tid,
                    Asd + (unsigned)((cur ^ 1) * 128 * AXS * 4),
                    Bsd + (unsigned)((cur ^ 1) * 16 * BXS * 4));
            CPCOMMIT();
        }
        g_mma(As + cur * 128 * AXS, Bs + cur * 16 * BXS, lane, wm, wn, d);
        if (k0 + 16 < 1024) CPWAITALL();
        __syncthreads();
    }
    if (!isV) {
        g_epilogue(d, C, N, row0, col0, lane, wm, wn);
    } else {
        #pragma unroll
        for (int mt = 0; mt < 2; mt++) {
            #pragma unroll
            for (int nt = 0; nt < 8; nt++) {
                int r = row0 + wm * 32 + mt * 16 + (lane >> 2);
                int cc = col0 + wn * 64 + nt * 8 + 2 * (lane & 3);
                v2store(v2, r,     cc,     d[mt][nt][0]);
                v2store(v2, r,     cc + 1, d[mt][nt][1]);
                v2store(v2, r + 8, cc,     d[mt][nt][2]);
                v2store(v2, r + 8, cc + 1, d[mt][nt][3]);
            }
        }
    }
}

// ---------------------------------------------------------------------------
// Dual GEMM (tf32 inputs): grid=(8,32), block=256.
// ---------------------------------------------------------------------------
__global__ __launch_bounds__(256, 2)
void dual_gemm_kernel(const uint32_t* __restrict__ A1, const uint32_t* __restrict__ B1, int K1,
                      const uint32_t* __restrict__ A2, const uint32_t* __restrict__ B2, int K2,
                      float* __restrict__ C, int N) {
    extern __shared__ uint32_t gsm[];
    uint32_t* As = gsm;
    uint32_t* Bs = gsm + 2 * 128 * AXS;
    int tid = threadIdx.x;
    int lane = tid & 31, warp = tid >> 5;
    int wm = warp >> 1, wn = warp & 1;
    int row0 = blockIdx.y * 128, col0 = blockIdx.x * 128;
    float d[2][8][4] = {};
    unsigned Asd = su32(As), Bsd = su32(Bs);
    #pragma unroll
    for (int ph = 0; ph < 2; ph++) {
        const uint32_t* A = ph ? A2 : A1;
        const uint32_t* B = ph ? B2 : B1;
        int K = ph ? K2 : K1;
        g_issue(A, B, K, N, row0, col0, 0, tid, Asd, Bsd);
        CPCOMMIT(); CPWAITALL();
        __syncthreads();
        for (int k0 = 0; k0 < K; k0 += 16) {
            int cur = (k0 >> 4) & 1;
            if (k0 + 16 < K) {
                g_issue(A, B, K, N, row0, col0, k0 + 16, tid,
                        Asd + (unsigned)((cur ^ 1) * 128 * AXS * 4),
                        Bsd + (unsigned)((cur ^ 1) * 16 * BXS * 4));
                CPCOMMIT();
            }
            g_mma(As + cur * 128 * AXS, Bs + cur * 16 * BXS, lane, wm, wn, d);
            if (k0 + 16 < K) CPWAITALL();
            __syncthreads();
        }
    }
    g_epilogue(d, C, N, row0, col0, lane, wm, wn);
}

// ---------------------------------------------------------------------------
// RoPE (smem inv-freq table).
// ---------------------------------------------------------------------------
#define QSCALE 0.18033688f   // 0.125 * log2(e)

__global__ void rope_kernel(const float* __restrict__ qp, const float* __restrict__ kp,
                            uint32_t* __restrict__ q2, uint32_t* __restrict__ k2) {
    __shared__ float sinv[32];
    if (threadIdx.x < 32)
        sinv[threadIdx.x] = powf(500000.0f, -(float)(2 * threadIdx.x) / 64.0f);
    __syncthreads();
    int idx = blockIdx.x * blockDim.x + threadIdx.x;
    const int qtot = Bsz * Sl * Hn * 32;
    const int ktot = Bsz * Sl * HKn * 32;
    const float* src; uint32_t* dst; int nheads; bool isq;
    if (idx < qtot) { src = qp; dst = q2; nheads = Hn; isq = true; }
    else { idx -= qtot; if (idx >= ktot) return; src = kp; dst = k2; nheads = HKn; isq = false; }
    int j = idx & 31;
    int h = (idx >> 5) % nheads;
    int s = ((idx >> 5) / nheads) % Sl;
    int b = idx / (32 * nheads * Sl);
    float ang = (float)s * sinv[j];
    float c, sn;
    __sincosf(ang, &sn, &c);
    size_t base = ((size_t)(b * Sl + s) * nheads + h) * 64;
    float u1 = src[base + j], u2 = src[base + j + 32];
    float r1 = u1 * c - u2 * sn;
    float r2 = u2 * c + u1 * sn;
    if (isq) { r1 *= QSCALE; r2 *= QSCALE; }
    dst[base + colperm(j)]      = f2tf(r1);
    dst[base + colperm(j + 32)] = f2tf(r2);
}

// ---------------------------------------------------------------------------
// TF32 flash attention v6 (R15 best): no-max softmax, raw-bit P, l via
// ones-column mma, sigma-permuted V. 128 threads, 2 CTAs/SM.
// ---------------------------------------------------------------------------
#define QST 72
#define KST 72
#define VST 144
#define ATTN_WORDS (128*QST + 2*64*KST + 2*32*VST)
#define ATTN_BYTES (ATTN_WORDS * 4)
#define TF_ONE 0x3F800000u

__global__ __launch_bounds__(128, 2)
void attn_kernel(const uint32_t* __restrict__ q2, const uint32_t* __restrict__ k2,
                 const uint32_t* __restrict__ v2, uint32_t* __restrict__ o2) {
    extern __shared__ uint32_t smu[];
    uint32_t* qs = smu;
    uint32_t* ks = qs + 128 * QST;
    uint32_t* vs = ks + 2 * 64 * KST;

    int qt = (int)gridDim.x - 1 - (int)blockIdx.x;
    int bh = blockIdx.y;
    int b = bh >> 4, h = bh & 15, kh = h >> 2;
    int tid = threadIdx.x;
    int lane = tid & 31, w = tid >> 5;
    int g = lane >> 2, c4 = lane & 3;
    int row_base = w * 32 + g;

    size_t qbase = ((size_t)(b * Sl + qt * 128) * Hn + h) * 64;
    size_t kvbase = ((size_t)(b * Sl) * HKn + kh) * 64;
    size_t v2base0 = (size_t)(b * HKn + kh) * (Sl / 2) * 128;
    int ktmax = 2 * qt + 1;

    {
        unsigned qd = su32(qs);
        #pragma unroll
        for (int i = 0; i < 16; i++) {
            int vec = tid + i * 128;
            int r = vec >> 4, ch = vec & 15;
            CP16(qd + (unsigned)((r * QST + ch * 4) * 4),
                 &q2[qbase + (size_t)r * Hn * 64 + ch * 4]);
        }
        unsigned kd = su32(ks), vd = su32(vs);
        #pragma unroll
        for (int i = 0; i < 8; i++) {
            int vec = tid + i * 128;
            int c = vec >> 4, dq = vec & 15;
            CP16(kd + (unsigned)((c * KST + dq * 4) * 4),
                 &k2[kvbase + (size_t)c * HKn * 64 + dq * 4]);
            int row = vec >> 5, ch = vec & 31;
            CP16(vd + (unsigned)((row * VST + ch * 4) * 4),
                 &v2[v2base0 + (size_t)row * 128 + ch * 4]);
        }
        CPCOMMIT();
    }

    float accL[2][4] = {};
    float accO[2][8][4] = {};
    const uint32_t bones[2] = { TF_ONE, TF_ONE };
    CPWAITALL();
    __syncthreads();

    for (int kt = 0; kt <= ktmax; kt++) {
        const uint32_t* kb = ks + (kt & 1) * 64 * KST;
        const uint32_t* vb = vs + (kt & 1) * 32 * VST;

        if (kt < ktmax) {
            unsigned kd = su32(ks + ((kt + 1) & 1) * 64 * KST);
            unsigned vd = su32(vs + ((kt + 1) & 1) * 32 * VST);
            size_t kbase = kvbase + (size_t)(kt + 1) * 64 * HKn * 64;
            size_t vbase = v2base0 + (size_t)(kt + 1) * 32 * 128;
            #pragma unroll
            for (int i = 0; i < 8; i++) {
                int vec = tid + i * 128;
                int c = vec >> 4, dq = vec & 15;
                CP16(kd + (unsigned)((c * KST + dq * 4) * 4),
                     &k2[kbase + (size_t)c * HKn * 64 + dq * 4]);
                int row = vec >> 5, ch = vec & 31;
                CP16(vd + (unsigned)((row * VST + ch * 4) * 4),
                     &v2[vbase + (size_t)row * 128 + ch * 4]);
            }
            CPCOMMIT();
        }

        // ---- QK^T ----
        float sc[2][8][4] = {};
        #pragma unroll
        for (int t8 = 0; t8 < 8; t8++) {
            int pc = t8 * 8 + 2 * c4;
            uint32_t a[2][4];
            #pragma unroll
            for (int mt = 0; mt < 2; mt++) {
                uint2 ua0 = *(const uint2*)&qs[(row_base + mt * 16) * QST + pc];
                uint2 ua1 = *(const uint2*)&qs[(row_base + mt * 16 + 8) * QST + pc];
                a[mt][0] = ua0.x; a[mt][1] = ua1.x; a[mt][2] = ua0.y; a[mt][3] = ua1.y;
            }
            #pragma unroll
            for (int nt = 0; nt < 8; nt++) {
                int n = nt * 8 + g;
                uint2 ub = *(const uint2*)&kb[n * KST + pc];
                uint32_t bb[2] = { ub.x, ub.y };
                mma8(sc[0][nt], a[0], bb);
                mma8(sc[1][nt], a[1], bb);
            }
        }

        // ---- causal mask ----
        if (kt >= 2 * qt) {
            #pragma unroll
            for (int mt = 0; mt < 2; mt++) {
                int rg0 = qt * 128 + row_base + mt * 16, rg1 = rg0 + 8;
                #pragma unroll
                for (int nt = 0; nt < 8; nt++) {
                    int cg = kt * 64 + nt * 8 + 2 * c4;
                    if (cg > rg0)     sc[mt][nt][0] = -1e30f;
                    if (cg + 1 > rg0) sc[mt][nt][1] = -1e30f;
                    if (cg > rg1)     sc[mt][nt][2] = -1e30f;
                    if (cg + 1 > rg1) sc[mt][nt][3] = -1e30f;
                }
            }
        }

        // ---- softmax numerator ----
        #pragma unroll
        for (int mt = 0; mt < 2; mt++)
            #pragma unroll
            for (int nt = 0; nt < 8; nt++) {
                sc[mt][nt][0] = ex2(sc[mt][nt][0]);
                sc[mt][nt][1] = ex2(sc[mt][nt][1]);
                sc[mt][nt][2] = ex2(sc[mt][nt][2]);
                sc[mt][nt][3] = ex2(sc[mt][nt][3]);
            }

        // ---- P @ V + l via ones-mma ----
        #pragma unroll
        for (int t = 0; t < 8; t++) {
            uint32_t a[2][4];
            #pragma unroll
            for (int mt = 0; mt < 2; mt++) {
                a[mt][0] = __float_as_uint(sc[mt][t][0]);
                a[mt][1] = __float_as_uint(sc[mt][t][2]);
                a[mt][2] = __float_as_uint(sc[mt][t][1]);
                a[mt][3] = __float_as_uint(sc[mt][t][3]);
            }
            int vrow = t * 4 + c4;
            #pragma unroll
            for (int nt = 0; nt < 8; nt++) {
                int dcol = nt * 8 + g;
                uint2 ub = *(const uint2*)&vb[vrow * VST + 2 * dcol];
                uint32_t bb[2] = { ub.x, ub.y };
                mma8(accO[0][nt], a[0], bb);
                mma8(accO[1][nt], a[1], bb);
            }
            mma8(accL[0], a[0], bones);
            mma8(accL[1], a[1], bones);
        }

        if (kt < ktmax) CPWAITALL();
        __syncthreads();
    }

    // ---- epilogue ----
    #pragma unroll
    for (int mt = 0; mt < 2; mt++) {
        float il0 = 1.f / accL[mt][0];
        float il1 = 1.f / accL[mt][2];
        size_t ob0 = ((size_t)(b * Sl + qt * 128 + row_base + mt * 16) * Hn + h) * 64;
        size_t ob1 = ((size_t)(b * Sl + qt * 128 + row_base + mt * 16 + 8) * Hn + h) * 64;
        #pragma unroll
        for (int nt = 0; nt < 8; nt++) {
            int dcol = nt * 8 + 2 * c4;
            uint2 u0, u1;
            u0.x = f2tf(accO[mt][nt][0] * il0); u0.y = f2tf(accO[mt][nt][1] * il0);
            u1.x = f2tf(accO[mt][nt][2] * il1); u1.y = f2tf(accO[mt][nt][3] * il1);
            *(uint2*)&o2[ob0 + dcol] = u0;
            *(uint2*)&o2[ob1 + dcol] = u1;
        }
    }
}

// ---------------------------------------------------------------------------
// Chunked delta-rule memory scan (side stream, after concurrent z-proj).
// ---------------------------------------------------------------------------
__global__ __launch_bounds__(256)
void memscan_kernel(const float* __restrict__ z,
                    const float* __restrict__ M_init,
                    const float* __restrict__ w_eta, const float* __restrict__ b_eta,
                    const float* __restrict__ w_alpha, const float* __restrict__ b_alpha,
                    const float* __restrict__ w_gate, const float* __restrict__ b_gate,
                    uint32_t* __restrict__ mem_out) {
    __shared__ float Ms[64][65];
    __shared__ float chs[64][65];
    __shared__ float red2[16][64];
    __shared__ float se[64], sa[64], sg[64], rnrm[64];
    __shared__ float kmean[64], vt[64], diffv[64];
    __shared__ float swe[64], swa[64], swg[64];
    __shared__ float redw[8];
    __shared__ float sc_eta, sc_alpha, sc_gate, sc_scale;

    int b = blockIdx.x;
    int tid = threadIdx.x;
    int tx = tid & 15, ty = tid >> 4;
    int lane = tid & 31, warp = tid >> 5;
    int tok = tid >> 2, part = tid & 3;
    float be = b_eta[0], ba = b_alpha[0], bg = b_gate[0];

    if (tid < 64) { swe[tid] = w_eta[tid]; swa[tid] = w_alpha[tid]; swg[tid] = w_gate[tid]; }
    #pragma unroll
    for (int i = 0; i < 16; i++) {
        int idx = tid + i * 256;
        Ms[idx >> 6][idx & 63] = M_init[idx];
    }
    __syncthreads();

    for (int c = 0; c < NCH; c++) {
        #pragma unroll
        for (int i = 0; i < 16; i++) {
            int idx = tid + i * 256;
            chs[idx >> 6][idx & 63] = z[((size_t)b * Sl + c * 64 + (idx >> 6)) * 64 + (idx & 63)];
        }
        __syncthreads();

        float o4[4][4] = {};
        #pragma unroll
        for (int d = 0; d < 64; d++) {
            float a0 = chs[ty*4+0][d], a1 = chs[ty*4+1][d];
            float a2 = chs[ty*4+2][d], a3 = chs[ty*4+3][d];
            float m0 = Ms[tx*4+0][d], m1 = Ms[tx*4+1][d];
            float m2 = Ms[tx*4+2][d], m3 = Ms[tx*4+3][d];
            o4[0][0] += a0*m0; o4[0][1] += a0*m1; o4[0][2] += a0*m2; o4[0][3] += a0*m3;
            o4[1][0] += a1*m0; o4[1][1] += a1*m1; o4[1][2] += a1*m2; o4[1][3] += a1*m3;
            o4[2][0] += a2*m0; o4[2][1] += a2*m1; o4[2][2] += a2*m2; o4[2][3] += a2*m3;
            o4[3][0] += a3*m0; o4[3][1] += a3*m1; o4[3][2] += a3*m2; o4[3][3] += a3*m3;
        }
        #pragma unroll
        for (int i = 0; i < 4; i++)
            #pragma unroll
            for (int j = 0; j < 4; j++)
                mem_out[((size_t)b * Sl + c * 64 + ty * 4 + i) * 64 + tx * 4 + j] = f2tf(o4[i][j]);
        #pragma unroll
        for (int j = 0; j < 4; j++)
            red2[ty][tx * 4 + j] = o4[0][j] + o4[1][j] + o4[2][j] + o4[3][j];
        __syncthreads();

        {
            float de = 0.f, da = 0.f, dg = 0.f, nn = 0.f;
            int d0 = part * 16;
            #pragma unroll
            for (int dd = 0; dd < 16; dd++) {
                float xv = chs[tok][d0 + dd];
                de = fmaf(xv, swe[d0 + dd], de);
                da = fmaf(xv, swa[d0 + dd], da);
                dg = fmaf(xv, swg[d0 + dd], dg);
                nn = fmaf(xv, xv, nn);
            }
            de += __shfl_xor_sync(0xffffffffu, de, 1); de += __shfl_xor_sync(0xffffffffu, de, 2);
            da += __shfl_xor_sync(0xffffffffu, da, 1); da += __shfl_xor_sync(0xffffffffu, da, 2);
            dg += __shfl_xor_sync(0xffffffffu, dg, 1); dg += __shfl_xor_sync(0xffffffffu, dg, 2);
            nn += __shfl_xor_sync(0xffffffffu, nn, 1); nn += __shfl_xor_sync(0xffffffffu, nn, 2);
            if (part == 0) {
                se[tok] = 0.2f / (1.f + __expf(-(de + be)));
                sa[tok] = 0.5f + 0.5f / (1.f + __expf(-(da + ba)));
                sg[tok] = 1.f / (1.f + __expf(-(dg + bg)));
                rnrm[tok] = 1.f / fmaxf(sqrtf(nn), 1e-6f);
            }
        }
        __syncthreads();

        {
            float s = 0.f, s2 = 0.f;
            #pragma unroll
            for (int t = 0; t < 16; t++)
                s = fmaf(chs[part * 16 + t][tok], rnrm[part * 16 + t], s);
            #pragma unroll
            for (int yy = 0; yy < 4; yy++) s2 += red2[part * 4 + yy][tok];
            s  += __shfl_xor_sync(0xffffffffu, s, 1);  s  += __shfl_xor_sync(0xffffffffu, s, 2);
            s2 += __shfl_xor_sync(0xffffffffu, s2, 1); s2 += __shfl_xor_sync(0xffffffffu, s2, 2);
            if (part == 0) { kmean[tok] = s * (1.f / 64.f); vt[tok] = s2 * (1.f / 64.f); }
        }
        __syncthreads();

        if (tid < 32) {
            float e = se[tid] + se[tid + 32];
            float a = sa[tid] + sa[tid + 32];
            float gg = sg[tid] + sg[tid + 32];
            #pragma unroll
            for (int st = 16; st; st >>= 1) {
                e  += __shfl_xor_sync(0xffffffffu, e, st);
                a  += __shfl_xor_sync(0xffffffffu, a, st);
                gg += __shfl_xor_sync(0xffffffffu, gg, st);
            }
            if (tid == 0) {
                sc_eta = e * (1.f / 64.f);
                sc_alpha = a * (1.f / 64.f);
                sc_gate = gg * (1.f / 64.f);
            }
        }
        {
            float s = 0.f;
            int d0 = part * 16;
            #pragma unroll
            for (int dd = 0; dd < 16; dd++)
                s = fmaf(Ms[tok][d0 + dd], kmean[d0 + dd], s);
            s += __shfl_xor_sync(0xffffffffu, s, 1);
            s += __shfl_xor_sync(0xffffffffu, s, 2);
            if (part == 0) diffv[tok] = vt[tok] - s;
        }
        __syncthreads();

        float eg = sc_eta * sc_gate, al = sc_alpha;
        float ss2 = 0.f;
        #pragma unroll
        for (int i = 0; i < 16; i++) {
            int idx = tid + i * 256;
            int vv = idx >> 6, d = idx & 63;
            float mn = al * Ms[vv][d] + eg * diffv[vv] * kmean[d];
            Ms[vv][d] = mn;
            ss2 = fmaf(mn, mn, ss2);
        }
        #pragma unroll
        for (int st = 16; st; st >>= 1) ss2 += __shfl_xor_sync(0xffffffffu, ss2, st);
        if (lane == 0) redw[warp] = ss2;
        __syncthreads();
        if (tid == 0) {
            float fro = sqrtf(redw[0] + redw[1] + redw[2] + redw[3] +
                              redw[4] + redw[5] + redw[6] + redw[7]);
            sc_scale = fminf(1.f, 30.f / fmaxf(fro, 1e-6f));
        }
        __syncthreads();
        #pragma unroll
        for (int i = 0; i < 16; i++) {
            int idx = tid + i * 256;
            Ms[idx >> 6][idx & 63] *= sc_scale;
        }
        __syncthreads();
    }
}

// ---------------------------------------------------------------------------
extern "C" void kernel_launch(void* const* d_in, const int* in_sizes, int n_in,
                              void* d_out, int out_size) {
    const float* x       = (const float*)d_in[0];
    const float* Wq      = (const float*)d_in[1];
    const float* Wk      = (const float*)d_in[2];
    const float* Wv      = (const float*)d_in[3];
    const float* Wo      = (const float*)d_in[4];
    const float* Wmemin  = (const float*)d_in[5];
    const float* Wmemout = (const float*)d_in[6];
    const float* M_init  = (const float*)d_in[7];
    const float* w_eta   = (const float*)d_in[8];
    const float* b_eta   = (const float*)d_in[9];
    const float* w_alpha = (const float*)d_in[10];
    const float* b_alpha = (const float*)d_in[11];
    const float* w_gate  = (const float*)d_in[12];
    const float* b_gate  = (const float*)d_in[13];
    float* out = (float*)d_out;

    float *q, *k, *z;
    uint32_t *attn2, *mem2, *q2, *k2, *v2;
    uint32_t *x2, *wq2, *wk2, *wv2, *wz2, *wo2, *wmo2;
    cudaGetSymbolAddress((void**)&q, g_q);
    cudaGetSymbolAddress((void**)&k, g_k);
    cudaGetSymbolAddress((void**)&z, g_z);
    cudaGetSymbolAddress((void**)&attn2, g_attn2);
    cudaGetSymbolAddress((void**)&mem2, g_mem2);
    cudaGetSymbolAddress((void**)&q2, g_q2);
    cudaGetSymbolAddress((void**)&k2, g_k2);
    cudaGetSymbolAddress((void**)&v2, g_v2);
    cudaGetSymbolAddress((void**)&x2, g_x2);
    cudaGetSymbolAddress((void**)&wq2, g_wq2);
    cudaGetSymbolAddress((void**)&wk2, g_wk2);
    cudaGetSymbolAddress((void**)&wv2, g_wv2);
    cudaGetSymbolAddress((void**)&wz2, g_wz2);
    cudaGetSymbolAddress((void**)&wo2, g_wo2);
    cudaGetSymbolAddress((void**)&wmo2, g_wmo2);

    static cudaStream_t s2 = nullptr;
    static cudaEvent_t evA = nullptr, evM = nullptr;
    static int inited = 0;
    if (!inited) {
        cudaStreamCreateWithFlags(&s2, cudaStreamNonBlocking);
        cudaEventCreateWithFlags(&evA, cudaEventDisableTiming);
        cudaEventCreateWithFlags(&evM, cudaEventDisableTiming);
        cudaFuncSetAttribute(attn_kernel,
                             cudaFuncAttributeMaxDynamicSharedMemorySize, ATTN_BYTES);
        cudaFuncSetAttribute(proj_kernel,
                             cudaFuncAttributeMaxDynamicSharedMemorySize, GEMM_SM_BYTES);
        cudaFuncSetAttribute(dual_gemm_kernel,
                             cudaFuncAttributeMaxDynamicSharedMemorySize, GEMM_SM_BYTES);
        inited = 1;
    }

    // Side stream: convert output-GEMM weights (off critical path).
    {
        int total4 = (Hn*HDn*Dm + DVn*Dm) / 4;
        cvtB_kernel<<<(total4 + 255) / 256, 256, 0, s2>>>(Wo, Wmemout, wo2, wmo2);
    }
    // Critical path: convert x + projection weights.
    {
        int total4 = (Bsz*Sl*Dm + Dm*Hn*HDn + 2*Dm*HKn*HDn + Dm*DKn) / 4;
        cvtA_kernel<<<(total4 + 255) / 256, 256>>>(x, Wq, Wk, Wv, Wmemin,
                                                   x2, wq2, wk2, wv2, wz2);
    }
    cudaEventRecord(evA, 0);

    // Side stream: z-GEMM runs CONCURRENTLY with the main proj, then memscan.
    cudaStreamWaitEvent(s2, evA, 0);
    proj_kernel<<<dim3(1, 32), 256, GEMM_SM_BYTES, s2>>>(x2, wq2, wk2, wv2, wz2,
                                                         q, k, v2, z, 12);
    memscan_kernel<<<Bsz, 256, 0, s2>>>(z, M_init, w_eta, b_eta, w_alpha, b_alpha,
                                        w_gate, b_gate, mem2);
    cudaEventRecord(evM, s2);

    // Main stream: projections (q, k, v)
    proj_kernel<<<dim3(12, 32), 256, GEMM_SM_BYTES>>>(x2, wq2, wk2, wv2, wz2,
                                                      q, k, v2, z, 0);

    // RoPE + tf32 convert + permute
    {
        int total = Bsz * Sl * (Hn + HKn) * 32;
        rope_kernel<<<(total + 255) / 256, 256>>>(q, k, q2, k2);
    }

    // Attention
    attn_kernel<<<dim3(Sl/128, Bsz*Hn), 128, ATTN_BYTES>>>(q2, k2, v2, attn2);

    // Join memscan (and cvtB), then fused output GEMM
    cudaStreamWaitEvent((cudaStream_t)0, evM, 0);
    dual_gemm_kernel<<<dim3(8, 32), 256, GEMM_SM_BYTES>>>(attn2, wo2, Hn*HDn,
                                                          mem2, wmo2, DVn, out, Dm);
}